// round 7
// baseline (speedup 1.0000x reference)
#include <cuda_runtime.h>
#include <math.h>

// ---------------------------------------------------------------------------
// N=100000, F_in=128, F_hid=64, F_out=40, E=1600000 (+N self loops).
// ---------------------------------------------------------------------------
#define MAXN 100000
#define MAXE 1700096

__device__ float g_h1[(size_t)MAXN * 64];
__device__ float g_h1r[(size_t)MAXN * 64];
__device__ float g_h2[(size_t)MAXN * 40];
__device__ float g_as[MAXN];
__device__ float g_ad[MAXN];
__device__ float g_den[MAXN];
__device__ float g_exc[MAXE];
__device__ int   g_idx[2 * 1600000];
__device__ int   g_cnt[MAXN];
__device__ int   g_off[MAXN + 1];
__device__ int   g_cur[MAXN];
__device__ int   g_srcs[MAXE];
__device__ int   g_dsts[MAXE];
__device__ int   g_bsum[128];
__device__ int   g_is64;

// ---------------------------------------------------------------------------
// Edge index dtype detection + conversion, dst histogram fused.
// ---------------------------------------------------------------------------
__global__ void detect_idx_kernel(const unsigned int* __restrict__ w, int* flag) {
    __shared__ int any;
    if (threadIdx.x == 0) any = 0;
    __syncthreads();
    for (int i = threadIdx.x; i < 1024; i += blockDim.x)
        if (w[2 * i + 1] != 0u) atomicOr(&any, 1);
    __syncthreads();
    if (threadIdx.x == 0) *flag = any ? 0 : 1;  // 1 => int64
}

__global__ void init_cnt_kernel(int* cnt, float* den, int n) {
    int i = blockIdx.x * blockDim.x + threadIdx.x;
    if (i < n) { cnt[i] = 1; den[i] = 0.f; }  // cnt=1 for self loop
}

__global__ void convert_hist_kernel(const unsigned int* __restrict__ w,
                                    int* __restrict__ out, int* __restrict__ cnt,
                                    long long n2, long long E,
                                    const int* __restrict__ flag) {
    long long i = (long long)blockIdx.x * blockDim.x + threadIdx.x;
    if (i >= n2) return;
    int is64 = *flag;
    int v = (int)(is64 ? w[2 * i] : w[i]);
    out[i] = v;
    if (i >= E) atomicAdd(&cnt[v], 1);
}

// ---------------------------------------------------------------------------
// Two-level exclusive scan of cnt -> off
// ---------------------------------------------------------------------------
__global__ void scanA_kernel(const int* __restrict__ cnt, int* __restrict__ off,
                             int* __restrict__ bsum, int n) {
    __shared__ int sm[1024];
    int i = blockIdx.x * 1024 + threadIdx.x;
    int v = (i < n) ? cnt[i] : 0;
    sm[threadIdx.x] = v;
    __syncthreads();
    #pragma unroll
    for (int o = 1; o < 1024; o <<= 1) {
        int t = (threadIdx.x >= o) ? sm[threadIdx.x - o] : 0;
        __syncthreads();
        sm[threadIdx.x] += t;
        __syncthreads();
    }
    if (i < n) off[i] = sm[threadIdx.x] - v;
    if (threadIdx.x == 1023) bsum[blockIdx.x] = sm[1023];
}

__global__ void scanB_kernel(int* bsum, int nb) {
    __shared__ int sm[128];
    int v = (threadIdx.x < nb) ? bsum[threadIdx.x] : 0;
    sm[threadIdx.x] = v;
    __syncthreads();
    #pragma unroll
    for (int o = 1; o < 128; o <<= 1) {
        int t = (threadIdx.x >= o) ? sm[threadIdx.x - o] : 0;
        __syncthreads();
        sm[threadIdx.x] += t;
        __syncthreads();
    }
    if (threadIdx.x < nb) bsum[threadIdx.x] = sm[threadIdx.x] - v;
}

__global__ void scanC_kernel(int* __restrict__ off, int* __restrict__ cur,
                             const int* __restrict__ bsum, int n, int total) {
    int i = blockIdx.x * blockDim.x + threadIdx.x;
    if (i < n) {
        int o = off[i] + bsum[i >> 10];
        off[i] = o;
        cur[i] = o;
    }
    if (i == 0) off[n] = total;
}

__global__ void fill_kernel(const int* __restrict__ idx, int* __restrict__ cur,
                            int* __restrict__ srcs, int* __restrict__ dsts,
                            long long E, long long T) {
    long long t = (long long)blockIdx.x * blockDim.x + threadIdx.x;
    if (t >= T) return;
    int s, d;
    if (t < E) { s = idx[t]; d = idx[t + E]; } else { s = d = (int)(t - E); }
    int pos = atomicAdd(&cur[d], 1);
    srcs[pos] = s;
    dsts[pos] = d;
}

// ---------------------------------------------------------------------------
// Edge-parallel softmax numerators: exc[i] = exp(lrelu(as[src]+ad[dst])),
// den[dst] += exc[i]. Fully parallel, high MLP.
// ---------------------------------------------------------------------------
__global__ void coef_kernel(const int* __restrict__ srcs,
                            const int* __restrict__ dsts,
                            const float* __restrict__ as_,
                            const float* __restrict__ ad_,
                            float* __restrict__ exc, float* __restrict__ den,
                            long long T) {
    long long i = (long long)blockIdx.x * blockDim.x + threadIdx.x;
    if (i >= T) return;
    int s = srcs[i], d = dsts[i];
    float e = as_[s] + ad_[d];
    e = (e > 0.f) ? e : 0.2f * e;
    float ex = expf(e);
    exc[i] = ex;
    atomicAdd(&den[d], ex);
}

__global__ void rden_kernel(float* den, int n) {
    int i = blockIdx.x * blockDim.x + threadIdx.x;
    if (i < n) den[i] = 1.0f / den[i];
}

// ---------------------------------------------------------------------------
// GEMM1: h = x @ W (K=128, C=64), 128x64/block, 128 threads, 8x8/thread,
// packed f32x2 FMAs, alpha dots fused into epilogue.
// ---------------------------------------------------------------------------
__global__ void gemm1_kernel(const float* __restrict__ x,
                             const float* __restrict__ W,
                             const float* __restrict__ asv,
                             const float* __restrict__ adv,
                             float* __restrict__ h,
                             float* __restrict__ as_, float* __restrict__ ad_,
                             int Nn) {
    __shared__ float Xs[128 * 32];
    __shared__ float Ws[32 * 64];
    int tid = threadIdx.x;
    int row0 = blockIdx.x * 128;
    int rt = tid >> 3;
    int ct = tid & 7;
    int r0 = rt * 8;
    int kx = (rt & 3) << 3;

    unsigned long long acc[8][4];
    #pragma unroll
    for (int i = 0; i < 8; i++)
        #pragma unroll
        for (int j = 0; j < 4; j++) acc[i][j] = 0ull;

    const float4* x4 = (const float4*)x;

    for (int kc = 0; kc < 4; kc++) {
        const float4* W4 = (const float4*)(W + kc * 32 * 64);
        #pragma unroll
        for (int i = tid; i < 512; i += 128) ((float4*)Ws)[i] = W4[i];
        #pragma unroll
        for (int i = tid; i < 1024; i += 128) {
            int row = i >> 3;
            int c4  = i & 7;
            int gr = row0 + row;
            float4 v = (gr < Nn) ? x4[(size_t)gr * 32 + kc * 8 + c4]
                                 : make_float4(0.f, 0.f, 0.f, 0.f);
            int col = (c4 * 4) ^ (((row >> 3) & 3) << 3);
            *(float4*)&Xs[row * 32 + col] = v;
        }
        __syncthreads();

        #pragma unroll
        for (int k = 0; k < 32; k++) {
            longlong2 w0 = *(const longlong2*)&Ws[k * 64 + ct * 8];
            longlong2 w1 = *(const longlong2*)&Ws[k * 64 + ct * 8 + 4];
            #pragma unroll
            for (int i = 0; i < 8; i++) {
                float xv = Xs[(r0 + i) * 32 + (k ^ kx)];
                unsigned long long xx;
                asm("mov.b64 %0, {%1, %1};" : "=l"(xx) : "r"(__float_as_uint(xv)));
                asm("fma.rn.f32x2 %0, %1, %2, %0;" : "+l"(acc[i][0]) : "l"(xx), "l"((unsigned long long)w0.x));
                asm("fma.rn.f32x2 %0, %1, %2, %0;" : "+l"(acc[i][1]) : "l"(xx), "l"((unsigned long long)w0.y));
                asm("fma.rn.f32x2 %0, %1, %2, %0;" : "+l"(acc[i][2]) : "l"(xx), "l"((unsigned long long)w1.x));
                asm("fma.rn.f32x2 %0, %1, %2, %0;" : "+l"(acc[i][3]) : "l"(xx), "l"((unsigned long long)w1.y));
            }
        }
        __syncthreads();
    }

    const float4* as4 = (const float4*)asv;
    const float4* ad4 = (const float4*)adv;
    float4 sa0 = as4[ct * 2], sa1 = as4[ct * 2 + 1];
    float4 da0 = ad4[ct * 2], da1 = ad4[ct * 2 + 1];

    #pragma unroll
    for (int i = 0; i < 8; i++) {
        int row = row0 + r0 + i;
        float o[8];
        #pragma unroll
        for (int j = 0; j < 4; j++) {
            unsigned int lo, hi;
            asm("mov.b64 {%0, %1}, %2;" : "=r"(lo), "=r"(hi) : "l"(acc[i][j]));
            o[2 * j]     = __uint_as_float(lo);
            o[2 * j + 1] = __uint_as_float(hi);
        }
        float ps = o[0]*sa0.x + o[1]*sa0.y + o[2]*sa0.z + o[3]*sa0.w
                 + o[4]*sa1.x + o[5]*sa1.y + o[6]*sa1.z + o[7]*sa1.w;
        float pd = o[0]*da0.x + o[1]*da0.y + o[2]*da0.z + o[3]*da0.w
                 + o[4]*da1.x + o[5]*da1.y + o[6]*da1.z + o[7]*da1.w;
        #pragma unroll
        for (int m = 1; m < 8; m <<= 1) {
            ps += __shfl_xor_sync(0xffffffffu, ps, m);
            pd += __shfl_xor_sync(0xffffffffu, pd, m);
        }
        if (row < Nn) {
            float* dstp = h + (size_t)row * 64 + ct * 8;
            *(float4*)dstp       = make_float4(o[0], o[1], o[2], o[3]);
            *(float4*)(dstp + 4) = make_float4(o[4], o[5], o[6], o[7]);
            if (ct == 0) { as_[row] = ps; ad_[row] = pd; }
        }
    }
}

// ---------------------------------------------------------------------------
// GEMM2: h2 = h1r @ W2 (K=64, C=40), alpha dots fused into epilogue.
// ---------------------------------------------------------------------------
__global__ void gemm2_kernel(const float* __restrict__ x,
                             const float* __restrict__ W,
                             const float* __restrict__ asv,
                             const float* __restrict__ adv,
                             float* __restrict__ h,
                             float* __restrict__ as_, float* __restrict__ ad_,
                             int Nn) {
    __shared__ float Xs[32][64];
    __shared__ float Ws[64][40];
    int tid = threadIdx.x;
    int row0 = blockIdx.x * 32;

    #pragma unroll
    for (int i = tid; i < 64 * 40; i += 128) Ws[i / 40][i % 40] = W[i];

    const float4* x4 = (const float4*)x;
    float4* Xs4 = (float4*)Xs;
    #pragma unroll
    for (int i = tid; i < 32 * 16; i += 128) {
        long long gi = (long long)row0 * 16 + i;
        Xs4[i] = (gi < (long long)Nn * 16) ? x4[gi] : make_float4(0.f, 0.f, 0.f, 0.f);
    }
    __syncthreads();

    int r0 = (tid >> 3) * 2;
    int c0 = (tid & 7) * 5;
    float acc[2][5] = {};
    #pragma unroll 4
    for (int k = 0; k < 64; k++) {
        float xv0 = Xs[r0][k];
        float xv1 = Xs[r0 + 1][k];
        #pragma unroll
        for (int j = 0; j < 5; j++) {
            float wv = Ws[k][c0 + j];
            acc[0][j] += xv0 * wv;
            acc[1][j] += xv1 * wv;
        }
    }

    float sa[5], da[5];
    #pragma unroll
    for (int j = 0; j < 5; j++) { sa[j] = asv[c0 + j]; da[j] = adv[c0 + j]; }

    #pragma unroll
    for (int i = 0; i < 2; i++) {
        int row = row0 + r0 + i;
        float ps = 0.f, pd = 0.f;
        #pragma unroll
        for (int j = 0; j < 5; j++) {
            ps += acc[i][j] * sa[j];
            pd += acc[i][j] * da[j];
        }
        #pragma unroll
        for (int m = 1; m < 8; m <<= 1) {
            ps += __shfl_xor_sync(0xffffffffu, ps, m);
            pd += __shfl_xor_sync(0xffffffffu, pd, m);
        }
        if (row < Nn) {
            float* dstp = h + (size_t)row * 40 + c0;
            #pragma unroll
            for (int j = 0; j < 5; j++) dstp[j] = acc[i][j];
            if ((tid & 7) == 0) { as_[row] = ps; ad_[row] = pd; }
        }
    }
}

// ---------------------------------------------------------------------------
// Pure gather aggregation, one warp per destination (CSR). Coefs precomputed.
// 8 edges per warp-iteration (2 per 8-lane subwarp), branchless clamp.
// Epilogue: FINAL=false -> relu(acc+bias); FINAL=true -> fused log_softmax.
// ---------------------------------------------------------------------------
template <int F, bool FINAL>
__global__ void gat_agg_kernel(const int* __restrict__ srcs,
                               const int* __restrict__ off,
                               const float* __restrict__ exc,
                               const float* __restrict__ rden,
                               const float* __restrict__ h,
                               const float* __restrict__ bias,
                               float* __restrict__ outp, int Nn) {
    constexpr int NV4 = F / 4;
    int lane = threadIdx.x & 31;
    int d = (blockIdx.x * blockDim.x + threadIdx.x) >> 5;
    if (d >= Nn) return;
    int beg = off[d], end = off[d + 1];
    int deg = end - beg;
    float rdenv = rden[d];

    int g = lane >> 3, l8 = lane & 7;
    float4 a0 = make_float4(0.f, 0.f, 0.f, 0.f);
    float4 a1 = make_float4(0.f, 0.f, 0.f, 0.f);
    const float4* h4 = (const float4*)h;
    const bool has1 = (F == 64) || (l8 < NV4 - 8);

    for (int it = 0; it < deg; it += 8) {
        int e0 = it + g;
        int e1 = it + 4 + g;
        int i0 = beg + min(e0, deg - 1);
        int i1 = beg + min(e1, deg - 1);
        int s0 = __ldg(&srcs[i0]);
        int s1 = __ldg(&srcs[i1]);
        float c0 = __ldg(&exc[i0]) * rdenv; if (e0 >= deg) c0 = 0.f;
        float c1 = __ldg(&exc[i1]) * rdenv; if (e1 >= deg) c1 = 0.f;
        const float4* r0p = h4 + (size_t)s0 * NV4;
        const float4* r1p = h4 + (size_t)s1 * NV4;
        float4 v00 = __ldg(&r0p[l8]);
        float4 v10 = __ldg(&r1p[l8]);
        float4 v01, v11;
        if (has1) { v01 = __ldg(&r0p[8 + l8]); v11 = __ldg(&r1p[8 + l8]); }
        a0.x = fmaf(v00.x, c0, a0.x); a0.y = fmaf(v00.y, c0, a0.y);
        a0.z = fmaf(v00.z, c0, a0.z); a0.w = fmaf(v00.w, c0, a0.w);
        a0.x = fmaf(v10.x, c1, a0.x); a0.y = fmaf(v10.y, c1, a0.y);
        a0.z = fmaf(v10.z, c1, a0.z); a0.w = fmaf(v10.w, c1, a0.w);
        if (has1) {
            a1.x = fmaf(v01.x, c0, a1.x); a1.y = fmaf(v01.y, c0, a1.y);
            a1.z = fmaf(v01.z, c0, a1.z); a1.w = fmaf(v01.w, c0, a1.w);
            a1.x = fmaf(v11.x, c1, a1.x); a1.y = fmaf(v11.y, c1, a1.y);
            a1.z = fmaf(v11.z, c1, a1.z); a1.w = fmaf(v11.w, c1, a1.w);
        }
    }

    // Combine the 4 subwarps
    #pragma unroll
    for (int m = 8; m < 32; m <<= 1) {
        a0.x += __shfl_xor_sync(0xffffffffu, a0.x, m);
        a0.y += __shfl_xor_sync(0xffffffffu, a0.y, m);
        a0.z += __shfl_xor_sync(0xffffffffu, a0.z, m);
        a0.w += __shfl_xor_sync(0xffffffffu, a0.w, m);
        a1.x += __shfl_xor_sync(0xffffffffu, a1.x, m);
        a1.y += __shfl_xor_sync(0xffffffffu, a1.y, m);
        a1.z += __shfl_xor_sync(0xffffffffu, a1.z, m);
        a1.w += __shfl_xor_sync(0xffffffffu, a1.w, m);
    }

    const float4* b4 = (const float4*)bias;
    if (!FINAL) {
        if (lane < 8) {
            float4 bb0 = b4[lane];
            float4 bb1 = b4[8 + lane];
            float4 o0 = make_float4(fmaxf(a0.x + bb0.x, 0.f), fmaxf(a0.y + bb0.y, 0.f),
                                    fmaxf(a0.z + bb0.z, 0.f), fmaxf(a0.w + bb0.w, 0.f));
            float4 o1 = make_float4(fmaxf(a1.x + bb1.x, 0.f), fmaxf(a1.y + bb1.y, 0.f),
                                    fmaxf(a1.z + bb1.z, 0.f), fmaxf(a1.w + bb1.w, 0.f));
            ((float4*)outp)[(size_t)d * NV4 + lane]     = o0;
            ((float4*)outp)[(size_t)d * NV4 + 8 + lane] = o1;
        }
    } else {
        float4 bb0 = b4[l8];
        float4 v0 = make_float4(a0.x + bb0.x, a0.y + bb0.y, a0.z + bb0.z, a0.w + bb0.w);
        float4 v1 = make_float4(0.f, 0.f, 0.f, 0.f);
        if (has1) {
            float4 bb1 = b4[8 + l8];
            v1 = make_float4(a1.x + bb1.x, a1.y + bb1.y, a1.z + bb1.z, a1.w + bb1.w);
        }
        float mx = fmaxf(fmaxf(v0.x, v0.y), fmaxf(v0.z, v0.w));
        if (has1) mx = fmaxf(mx, fmaxf(fmaxf(v1.x, v1.y), fmaxf(v1.z, v1.w)));
        #pragma unroll
        for (int m = 1; m < 8; m <<= 1) mx = fmaxf(mx, __shfl_xor_sync(0xffffffffu, mx, m));
        float se = expf(v0.x - mx) + expf(v0.y - mx) + expf(v0.z - mx) + expf(v0.w - mx);
        if (has1) se += expf(v1.x - mx) + expf(v1.y - mx) + expf(v1.z - mx) + expf(v1.w - mx);
        #pragma unroll
        for (int m = 1; m < 8; m <<= 1) se += __shfl_xor_sync(0xffffffffu, se, m);
        float ls = mx + logf(se);
        if (lane < 8)
            ((float4*)outp)[(size_t)d * NV4 + lane] =
                make_float4(v0.x - ls, v0.y - ls, v0.z - ls, v0.w - ls);
        if (lane < NV4 - 8)
            ((float4*)outp)[(size_t)d * NV4 + 8 + lane] =
                make_float4(v1.x - ls, v1.y - ls, v1.z - ls, v1.w - ls);
    }
}

// ---------------------------------------------------------------------------
// Launch: CSR build on side stream, overlapped with gemm1.
// ---------------------------------------------------------------------------
extern "C" void kernel_launch(void* const* d_in, const int* in_sizes, int n_in,
                              void* d_out, int out_size) {
    const float* x       = (const float*)d_in[0];
    const unsigned int* ei_raw = (const unsigned int*)d_in[1];
    const float* W1      = (const float*)d_in[2];
    const float* a_src1  = (const float*)d_in[3];
    const float* a_dst1  = (const float*)d_in[4];
    const float* b1      = (const float*)d_in[5];
    const float* W2      = (const float*)d_in[6];
    const float* a_src2  = (const float*)d_in[7];
    const float* a_dst2  = (const float*)d_in[8];
    const float* b2      = (const float*)d_in[9];
    float* out           = (float*)d_out;

    int Nn = in_sizes[0] / 128;
    long long E = in_sizes[1] / 2;
    long long T = E + Nn;

    float *p_h1, *p_h1r, *p_h2, *p_as, *p_ad, *p_den, *p_exc;
    int *p_idx, *p_cnt, *p_off, *p_cur, *p_srcs, *p_dsts, *p_bsum, *p_is64;
    cudaGetSymbolAddress((void**)&p_h1, g_h1);
    cudaGetSymbolAddress((void**)&p_h1r, g_h1r);
    cudaGetSymbolAddress((void**)&p_h2, g_h2);
    cudaGetSymbolAddress((void**)&p_as, g_as);
    cudaGetSymbolAddress((void**)&p_ad, g_ad);
    cudaGetSymbolAddress((void**)&p_den, g_den);
    cudaGetSymbolAddress((void**)&p_exc, g_exc);
    cudaGetSymbolAddress((void**)&p_idx, g_idx);
    cudaGetSymbolAddress((void**)&p_cnt, g_cnt);
    cudaGetSymbolAddress((void**)&p_off, g_off);
    cudaGetSymbolAddress((void**)&p_cur, g_cur);
    cudaGetSymbolAddress((void**)&p_srcs, g_srcs);
    cudaGetSymbolAddress((void**)&p_dsts, g_dsts);
    cudaGetSymbolAddress((void**)&p_bsum, g_bsum);
    cudaGetSymbolAddress((void**)&p_is64, g_is64);

    static cudaStream_t s2 = nullptr;
    static cudaEvent_t evF = nullptr, evC = nullptr;
    if (!s2) {
        cudaStreamCreateWithFlags(&s2, cudaStreamNonBlocking);
        cudaEventCreateWithFlags(&evF, cudaEventDisableTiming);
        cudaEventCreateWithFlags(&evC, cudaEventDisableTiming);
    }

    const int TB = 256;
    int nb = (Nn + 1023) / 1024;
    int edgeBlocks = (int)((T + TB - 1) / TB);

    // ---- Fork: CSR build on s2, gemm1 on main stream ----
    cudaEventRecord(evF, 0);
    cudaStreamWaitEvent(s2, evF, 0);

    detect_idx_kernel<<<1, 256, 0, s2>>>(ei_raw, p_is64);
    init_cnt_kernel<<<(Nn + TB - 1) / TB, TB, 0, s2>>>(p_cnt, p_den, Nn);
    convert_hist_kernel<<<(int)((2 * E + TB - 1) / TB), TB, 0, s2>>>(ei_raw, p_idx, p_cnt, 2 * E, E, p_is64);
    scanA_kernel<<<nb, 1024, 0, s2>>>(p_cnt, p_off, p_bsum, Nn);
    scanB_kernel<<<1, 128, 0, s2>>>(p_bsum, nb);
    scanC_kernel<<<(Nn + TB - 1) / TB, TB, 0, s2>>>(p_off, p_cur, p_bsum, Nn, (int)T);
    fill_kernel<<<edgeBlocks, TB, 0, s2>>>(p_idx, p_cur, p_srcs, p_dsts, E, T);
    cudaEventRecord(evC, s2);

    gemm1_kernel<<<(Nn + 127) / 128, 128>>>(x, W1, a_src1, a_dst1, p_h1, p_as, p_ad, Nn);

    // ---- Join ----
    cudaStreamWaitEvent(0, evC, 0);

    // Layer 1 softmax + gather
    coef_kernel<<<edgeBlocks, TB>>>(p_srcs, p_dsts, p_as, p_ad, p_exc, p_den, T);
    rden_kernel<<<(Nn + TB - 1) / TB, TB>>>(p_den, Nn);
    gat_agg_kernel<64, false><<<(Nn + 7) / 8, 256>>>(p_srcs, p_off, p_exc, p_den, p_h1, b1, p_h1r, Nn);

    // Layer 2
    gemm2_kernel<<<(Nn + 31) / 32, 128>>>(p_h1r, W2, a_src2, a_dst2, p_h2, p_as, p_ad, Nn);
    init_cnt_kernel<<<(Nn + TB - 1) / TB, TB>>>(p_cnt, p_den, Nn);  // re-zero den
    coef_kernel<<<edgeBlocks, TB>>>(p_srcs, p_dsts, p_as, p_ad, p_exc, p_den, T);
    rden_kernel<<<(Nn + TB - 1) / TB, TB>>>(p_den, Nn);
    gat_agg_kernel<40, true><<<(Nn + 7) / 8, 256>>>(p_srcs, p_off, p_exc, p_den, p_h2, b2, out, Nn);
}

// round 8
// speedup vs baseline: 1.0790x; 1.0790x over previous
#include <cuda_runtime.h>
#include <math.h>

// ---------------------------------------------------------------------------
// N=100000, F_in=128, F_hid=64, F_out=40, E=1600000 (+N self loops).
// ---------------------------------------------------------------------------
#define MAXN 100000
#define MAXE 1700096

__device__ float g_h1[(size_t)MAXN * 64];
__device__ float g_h1r[(size_t)MAXN * 64];
__device__ float g_h2[(size_t)MAXN * 40];
__device__ float g_as[MAXN];
__device__ float g_ad[MAXN];
__device__ int   g_idx[2 * 1600000];
__device__ int   g_cnt[MAXN];
__device__ int   g_off[MAXN + 1];
__device__ int   g_cur[MAXN];
__device__ int   g_srcs[MAXE];
__device__ int   g_bsum[128];
__device__ int   g_is64;

// ---------------------------------------------------------------------------
// Edge index dtype detection + conversion, dst histogram fused.
// ---------------------------------------------------------------------------
__global__ void detect_idx_kernel(const unsigned int* __restrict__ w, int* flag) {
    __shared__ int any;
    if (threadIdx.x == 0) any = 0;
    __syncthreads();
    for (int i = threadIdx.x; i < 1024; i += blockDim.x)
        if (w[2 * i + 1] != 0u) atomicOr(&any, 1);
    __syncthreads();
    if (threadIdx.x == 0) *flag = any ? 0 : 1;  // 1 => int64
}

__global__ void init_cnt_kernel(int* cnt, int n) {
    int i = blockIdx.x * blockDim.x + threadIdx.x;
    if (i < n) cnt[i] = 1;  // self loop
}

__global__ void convert_hist_kernel(const unsigned int* __restrict__ w,
                                    int* __restrict__ out, int* __restrict__ cnt,
                                    long long n2, long long E,
                                    const int* __restrict__ flag) {
    long long i = (long long)blockIdx.x * blockDim.x + threadIdx.x;
    if (i >= n2) return;
    int is64 = *flag;
    int v = (int)(is64 ? w[2 * i] : w[i]);
    out[i] = v;
    if (i >= E) atomicAdd(&cnt[v], 1);
}

// ---------------------------------------------------------------------------
// Two-level exclusive scan of cnt -> off
// ---------------------------------------------------------------------------
__global__ void scanA_kernel(const int* __restrict__ cnt, int* __restrict__ off,
                             int* __restrict__ bsum, int n) {
    __shared__ int sm[1024];
    int i = blockIdx.x * 1024 + threadIdx.x;
    int v = (i < n) ? cnt[i] : 0;
    sm[threadIdx.x] = v;
    __syncthreads();
    #pragma unroll
    for (int o = 1; o < 1024; o <<= 1) {
        int t = (threadIdx.x >= o) ? sm[threadIdx.x - o] : 0;
        __syncthreads();
        sm[threadIdx.x] += t;
        __syncthreads();
    }
    if (i < n) off[i] = sm[threadIdx.x] - v;
    if (threadIdx.x == 1023) bsum[blockIdx.x] = sm[1023];
}

__global__ void scanB_kernel(int* bsum, int nb) {
    __shared__ int sm[128];
    int v = (threadIdx.x < nb) ? bsum[threadIdx.x] : 0;
    sm[threadIdx.x] = v;
    __syncthreads();
    #pragma unroll
    for (int o = 1; o < 128; o <<= 1) {
        int t = (threadIdx.x >= o) ? sm[threadIdx.x - o] : 0;
        __syncthreads();
        sm[threadIdx.x] += t;
        __syncthreads();
    }
    if (threadIdx.x < nb) bsum[threadIdx.x] = sm[threadIdx.x] - v;
}

__global__ void scanC_kernel(int* __restrict__ off, int* __restrict__ cur,
                             const int* __restrict__ bsum, int n, int total) {
    int i = blockIdx.x * blockDim.x + threadIdx.x;
    if (i < n) {
        int o = off[i] + bsum[i >> 10];
        off[i] = o;
        cur[i] = o;
    }
    if (i == 0) off[n] = total;
}

__global__ void fill_kernel(const int* __restrict__ idx, int* __restrict__ cur,
                            int* __restrict__ srcs, long long E, long long T) {
    long long t = (long long)blockIdx.x * blockDim.x + threadIdx.x;
    if (t >= T) return;
    int s, d;
    if (t < E) { s = idx[t]; d = idx[t + E]; } else { s = d = (int)(t - E); }
    int pos = atomicAdd(&cur[d], 1);
    srcs[pos] = s;
}

// ---------------------------------------------------------------------------
// GEMM1: h = x @ W (K=128, C=64), 128x64/block, 128 threads, 8x8/thread,
// packed f32x2 FMAs, alpha dots fused into epilogue.
// ---------------------------------------------------------------------------
__global__ void gemm1_kernel(const float* __restrict__ x,
                             const float* __restrict__ W,
                             const float* __restrict__ asv,
                             const float* __restrict__ adv,
                             float* __restrict__ h,
                             float* __restrict__ as_, float* __restrict__ ad_,
                             int Nn) {
    __shared__ float Xs[128 * 32];
    __shared__ float Ws[32 * 64];
    int tid = threadIdx.x;
    int row0 = blockIdx.x * 128;
    int rt = tid >> 3;
    int ct = tid & 7;
    int r0 = rt * 8;
    int kx = (rt & 3) << 3;

    unsigned long long acc[8][4];
    #pragma unroll
    for (int i = 0; i < 8; i++)
        #pragma unroll
        for (int j = 0; j < 4; j++) acc[i][j] = 0ull;

    const float4* x4 = (const float4*)x;

    for (int kc = 0; kc < 4; kc++) {
        const float4* W4 = (const float4*)(W + kc * 32 * 64);
        #pragma unroll
        for (int i = tid; i < 512; i += 128) ((float4*)Ws)[i] = W4[i];
        #pragma unroll
        for (int i = tid; i < 1024; i += 128) {
            int row = i >> 3;
            int c4  = i & 7;
            int gr = row0 + row;
            float4 v = (gr < Nn) ? x4[(size_t)gr * 32 + kc * 8 + c4]
                                 : make_float4(0.f, 0.f, 0.f, 0.f);
            int col = (c4 * 4) ^ (((row >> 3) & 3) << 3);
            *(float4*)&Xs[row * 32 + col] = v;
        }
        __syncthreads();

        #pragma unroll
        for (int k = 0; k < 32; k++) {
            longlong2 w0 = *(const longlong2*)&Ws[k * 64 + ct * 8];
            longlong2 w1 = *(const longlong2*)&Ws[k * 64 + ct * 8 + 4];
            #pragma unroll
            for (int i = 0; i < 8; i++) {
                float xv = Xs[(r0 + i) * 32 + (k ^ kx)];
                unsigned long long xx;
                asm("mov.b64 %0, {%1, %1};" : "=l"(xx) : "r"(__float_as_uint(xv)));
                asm("fma.rn.f32x2 %0, %1, %2, %0;" : "+l"(acc[i][0]) : "l"(xx), "l"((unsigned long long)w0.x));
                asm("fma.rn.f32x2 %0, %1, %2, %0;" : "+l"(acc[i][1]) : "l"(xx), "l"((unsigned long long)w0.y));
                asm("fma.rn.f32x2 %0, %1, %2, %0;" : "+l"(acc[i][2]) : "l"(xx), "l"((unsigned long long)w1.x));
                asm("fma.rn.f32x2 %0, %1, %2, %0;" : "+l"(acc[i][3]) : "l"(xx), "l"((unsigned long long)w1.y));
            }
        }
        __syncthreads();
    }

    const float4* as4 = (const float4*)asv;
    const float4* ad4 = (const float4*)adv;
    float4 sa0 = as4[ct * 2], sa1 = as4[ct * 2 + 1];
    float4 da0 = ad4[ct * 2], da1 = ad4[ct * 2 + 1];

    #pragma unroll
    for (int i = 0; i < 8; i++) {
        int row = row0 + r0 + i;
        float o[8];
        #pragma unroll
        for (int j = 0; j < 4; j++) {
            unsigned int lo, hi;
            asm("mov.b64 {%0, %1}, %2;" : "=r"(lo), "=r"(hi) : "l"(acc[i][j]));
            o[2 * j]     = __uint_as_float(lo);
            o[2 * j + 1] = __uint_as_float(hi);
        }
        float ps = o[0]*sa0.x + o[1]*sa0.y + o[2]*sa0.z + o[3]*sa0.w
                 + o[4]*sa1.x + o[5]*sa1.y + o[6]*sa1.z + o[7]*sa1.w;
        float pd = o[0]*da0.x + o[1]*da0.y + o[2]*da0.z + o[3]*da0.w
                 + o[4]*da1.x + o[5]*da1.y + o[6]*da1.z + o[7]*da1.w;
        #pragma unroll
        for (int m = 1; m < 8; m <<= 1) {
            ps += __shfl_xor_sync(0xffffffffu, ps, m);
            pd += __shfl_xor_sync(0xffffffffu, pd, m);
        }
        if (row < Nn) {
            float* dstp = h + (size_t)row * 64 + ct * 8;
            *(float4*)dstp       = make_float4(o[0], o[1], o[2], o[3]);
            *(float4*)(dstp + 4) = make_float4(o[4], o[5], o[6], o[7]);
            if (ct == 0) { as_[row] = ps; ad_[row] = pd; }
        }
    }
}

// ---------------------------------------------------------------------------
// GEMM2: h2 = h1r @ W2 (K=64, C=40), alpha dots fused into epilogue.
// ---------------------------------------------------------------------------
__global__ void gemm2_kernel(const float* __restrict__ x,
                             const float* __restrict__ W,
                             const float* __restrict__ asv,
                             const float* __restrict__ adv,
                             float* __restrict__ h,
                             float* __restrict__ as_, float* __restrict__ ad_,
                             int Nn) {
    __shared__ float Xs[32][64];
    __shared__ float Ws[64][40];
    int tid = threadIdx.x;
    int row0 = blockIdx.x * 32;

    #pragma unroll
    for (int i = tid; i < 64 * 40; i += 128) Ws[i / 40][i % 40] = W[i];

    const float4* x4 = (const float4*)x;
    float4* Xs4 = (float4*)Xs;
    #pragma unroll
    for (int i = tid; i < 32 * 16; i += 128) {
        long long gi = (long long)row0 * 16 + i;
        Xs4[i] = (gi < (long long)Nn * 16) ? x4[gi] : make_float4(0.f, 0.f, 0.f, 0.f);
    }
    __syncthreads();

    int r0 = (tid >> 3) * 2;
    int c0 = (tid & 7) * 5;
    float acc[2][5] = {};
    #pragma unroll 4
    for (int k = 0; k < 64; k++) {
        float xv0 = Xs[r0][k];
        float xv1 = Xs[r0 + 1][k];
        #pragma unroll
        for (int j = 0; j < 5; j++) {
            float wv = Ws[k][c0 + j];
            acc[0][j] += xv0 * wv;
            acc[1][j] += xv1 * wv;
        }
    }

    float sa[5], da[5];
    #pragma unroll
    for (int j = 0; j < 5; j++) { sa[j] = asv[c0 + j]; da[j] = adv[c0 + j]; }

    #pragma unroll
    for (int i = 0; i < 2; i++) {
        int row = row0 + r0 + i;
        float ps = 0.f, pd = 0.f;
        #pragma unroll
        for (int j = 0; j < 5; j++) {
            ps += acc[i][j] * sa[j];
            pd += acc[i][j] * da[j];
        }
        #pragma unroll
        for (int m = 1; m < 8; m <<= 1) {
            ps += __shfl_xor_sync(0xffffffffu, ps, m);
            pd += __shfl_xor_sync(0xffffffffu, pd, m);
        }
        if (row < Nn) {
            float* dstp = h + (size_t)row * 40 + c0;
            #pragma unroll
            for (int j = 0; j < 5; j++) dstp[j] = acc[i][j];
            if ((tid & 7) == 0) { as_[row] = ps; ad_[row] = pd; }
        }
    }
}

// ---------------------------------------------------------------------------
// Fused GAT aggregation, one warp per destination (CSR).
// Pass 1: lane-parallel exp (cached in smem for deg<=96; else recompute).
// Pass 2: branchless batched gather, 16 edges per warp-iteration
// (4 per 8-lane subwarp) -> 8 independent LDG.128 in flight per lane.
// Epilogue: FINAL=false -> relu(acc+bias); FINAL=true -> fused log_softmax.
// ---------------------------------------------------------------------------
template <int F, bool FINAL>
__global__ void gat_agg_kernel(const int* __restrict__ srcs,
                               const int* __restrict__ off,
                               const float* __restrict__ as_,
                               const float* __restrict__ ad_,
                               const float* __restrict__ h,
                               const float* __restrict__ bias,
                               float* __restrict__ outp, int Nn) {
    constexpr int NV4 = F / 4;
    __shared__ float exco[8][100];
    int w = threadIdx.x >> 5, lane = threadIdx.x & 31;
    int d = blockIdx.x * 8 + w;
    if (d >= Nn) return;
    int beg = off[d], end = off[d + 1];
    int deg = end - beg;
    float advv = ad_[d];
    float* exc = exco[w];
    bool fits = (deg <= 96);

    // Pass 1
    float sum = 0.f;
    for (int i = lane; i < deg; i += 32) {
        int s = srcs[beg + i];
        float e = as_[s] + advv;
        e = (e > 0.f) ? e : 0.2f * e;
        float xv = __expf(e);
        if (fits) exc[i] = xv;
        sum += xv;
    }
    #pragma unroll
    for (int m = 16; m; m >>= 1) sum += __shfl_xor_sync(0xffffffffu, sum, m);
    float rden = 1.0f / sum;
    __syncwarp();

    int g = lane >> 3, l8 = lane & 7;
    float4 a0 = make_float4(0.f, 0.f, 0.f, 0.f);
    float4 a1 = make_float4(0.f, 0.f, 0.f, 0.f);
    const float4* h4 = (const float4*)h;
    const bool has1 = (F == 64) || (l8 < NV4 - 8);

    if (fits) {
        for (int it = 0; it < deg; it += 16) {
            int e[4], idx[4], s[4];
            float c[4];
            #pragma unroll
            for (int q = 0; q < 4; q++) {
                e[q] = it + q * 4 + g;
                idx[q] = min(e[q], deg - 1);
                s[q] = srcs[beg + idx[q]];
            }
            #pragma unroll
            for (int q = 0; q < 4; q++) {
                c[q] = exc[idx[q]] * rden;
                if (e[q] >= deg) c[q] = 0.f;
            }
            float4 v0[4], v1[4];
            #pragma unroll
            for (int q = 0; q < 4; q++) {
                const float4* rp = h4 + (size_t)s[q] * NV4;
                v0[q] = __ldg(&rp[l8]);
                if (has1) v1[q] = __ldg(&rp[8 + l8]);
            }
            #pragma unroll
            for (int q = 0; q < 4; q++) {
                a0.x = fmaf(v0[q].x, c[q], a0.x); a0.y = fmaf(v0[q].y, c[q], a0.y);
                a0.z = fmaf(v0[q].z, c[q], a0.z); a0.w = fmaf(v0[q].w, c[q], a0.w);
                if (has1) {
                    a1.x = fmaf(v1[q].x, c[q], a1.x); a1.y = fmaf(v1[q].y, c[q], a1.y);
                    a1.z = fmaf(v1[q].z, c[q], a1.z); a1.w = fmaf(v1[q].w, c[q], a1.w);
                }
            }
        }
    } else {
        for (int it = 0; it < deg; it += 4) {
            int e = it + g;
            if (e < deg) {
                int s = srcs[beg + e];
                float ev = as_[s] + advv;
                ev = (ev > 0.f) ? ev : 0.2f * ev;
                float coef = __expf(ev) * rden;
                const float4* row = h4 + (size_t)s * NV4;
                float4 v0 = __ldg(&row[l8]);
                a0.x = fmaf(v0.x, coef, a0.x); a0.y = fmaf(v0.y, coef, a0.y);
                a0.z = fmaf(v0.z, coef, a0.z); a0.w = fmaf(v0.w, coef, a0.w);
                if (has1) {
                    float4 v1 = __ldg(&row[8 + l8]);
                    a1.x = fmaf(v1.x, coef, a1.x); a1.y = fmaf(v1.y, coef, a1.y);
                    a1.z = fmaf(v1.z, coef, a1.z); a1.w = fmaf(v1.w, coef, a1.w);
                }
            }
        }
    }

    // Combine the 4 subwarps
    #pragma unroll
    for (int m = 8; m < 32; m <<= 1) {
        a0.x += __shfl_xor_sync(0xffffffffu, a0.x, m);
        a0.y += __shfl_xor_sync(0xffffffffu, a0.y, m);
        a0.z += __shfl_xor_sync(0xffffffffu, a0.z, m);
        a0.w += __shfl_xor_sync(0xffffffffu, a0.w, m);
        a1.x += __shfl_xor_sync(0xffffffffu, a1.x, m);
        a1.y += __shfl_xor_sync(0xffffffffu, a1.y, m);
        a1.z += __shfl_xor_sync(0xffffffffu, a1.z, m);
        a1.w += __shfl_xor_sync(0xffffffffu, a1.w, m);
    }

    const float4* b4 = (const float4*)bias;
    if (!FINAL) {
        if (lane < 8) {
            float4 bb0 = b4[lane];
            float4 bb1 = b4[8 + lane];
            float4 o0 = make_float4(fmaxf(a0.x + bb0.x, 0.f), fmaxf(a0.y + bb0.y, 0.f),
                                    fmaxf(a0.z + bb0.z, 0.f), fmaxf(a0.w + bb0.w, 0.f));
            float4 o1 = make_float4(fmaxf(a1.x + bb1.x, 0.f), fmaxf(a1.y + bb1.y, 0.f),
                                    fmaxf(a1.z + bb1.z, 0.f), fmaxf(a1.w + bb1.w, 0.f));
            ((float4*)outp)[(size_t)d * NV4 + lane]     = o0;
            ((float4*)outp)[(size_t)d * NV4 + 8 + lane] = o1;
        }
    } else {
        float4 bb0 = b4[l8];
        float4 v0 = make_float4(a0.x + bb0.x, a0.y + bb0.y, a0.z + bb0.z, a0.w + bb0.w);
        float4 v1 = make_float4(0.f, 0.f, 0.f, 0.f);
        if (has1) {
            float4 bb1 = b4[8 + l8];
            v1 = make_float4(a1.x + bb1.x, a1.y + bb1.y, a1.z + bb1.z, a1.w + bb1.w);
        }
        float mx = fmaxf(fmaxf(v0.x, v0.y), fmaxf(v0.z, v0.w));
        if (has1) mx = fmaxf(mx, fmaxf(fmaxf(v1.x, v1.y), fmaxf(v1.z, v1.w)));
        #pragma unroll
        for (int m = 1; m < 8; m <<= 1) mx = fmaxf(mx, __shfl_xor_sync(0xffffffffu, mx, m));
        float se = __expf(v0.x - mx) + __expf(v0.y - mx) + __expf(v0.z - mx) + __expf(v0.w - mx);
        if (has1) se += __expf(v1.x - mx) + __expf(v1.y - mx) + __expf(v1.z - mx) + __expf(v1.w - mx);
        #pragma unroll
        for (int m = 1; m < 8; m <<= 1) se += __shfl_xor_sync(0xffffffffu, se, m);
        float ls = mx + __logf(se);
        if (lane < 8)
            ((float4*)outp)[(size_t)d * NV4 + lane] =
                make_float4(v0.x - ls, v0.y - ls, v0.z - ls, v0.w - ls);
        if (lane < NV4 - 8)
            ((float4*)outp)[(size_t)d * NV4 + 8 + lane] =
                make_float4(v1.x - ls, v1.y - ls, v1.z - ls, v1.w - ls);
    }
}

// ---------------------------------------------------------------------------
// Launch: CSR build runs on a side stream, overlapped with gemm1.
// ---------------------------------------------------------------------------
extern "C" void kernel_launch(void* const* d_in, const int* in_sizes, int n_in,
                              void* d_out, int out_size) {
    const float* x       = (const float*)d_in[0];
    const unsigned int* ei_raw = (const unsigned int*)d_in[1];
    const float* W1      = (const float*)d_in[2];
    const float* a_src1  = (const float*)d_in[3];
    const float* a_dst1  = (const float*)d_in[4];
    const float* b1      = (const float*)d_in[5];
    const float* W2      = (const float*)d_in[6];
    const float* a_src2  = (const float*)d_in[7];
    const float* a_dst2  = (const float*)d_in[8];
    const float* b2      = (const float*)d_in[9];
    float* out           = (float*)d_out;

    int Nn = in_sizes[0] / 128;
    long long E = in_sizes[1] / 2;
    long long T = E + Nn;

    float *p_h1, *p_h1r, *p_h2, *p_as, *p_ad;
    int *p_idx, *p_cnt, *p_off, *p_cur, *p_srcs, *p_bsum, *p_is64;
    cudaGetSymbolAddress((void**)&p_h1, g_h1);
    cudaGetSymbolAddress((void**)&p_h1r, g_h1r);
    cudaGetSymbolAddress((void**)&p_h2, g_h2);
    cudaGetSymbolAddress((void**)&p_as, g_as);
    cudaGetSymbolAddress((void**)&p_ad, g_ad);
    cudaGetSymbolAddress((void**)&p_idx, g_idx);
    cudaGetSymbolAddress((void**)&p_cnt, g_cnt);
    cudaGetSymbolAddress((void**)&p_off, g_off);
    cudaGetSymbolAddress((void**)&p_cur, g_cur);
    cudaGetSymbolAddress((void**)&p_srcs, g_srcs);
    cudaGetSymbolAddress((void**)&p_bsum, g_bsum);
    cudaGetSymbolAddress((void**)&p_is64, g_is64);

    static cudaStream_t s2 = nullptr;
    static cudaEvent_t evF = nullptr, evC = nullptr;
    if (!s2) {
        cudaStreamCreateWithFlags(&s2, cudaStreamNonBlocking);
        cudaEventCreateWithFlags(&evF, cudaEventDisableTiming);
        cudaEventCreateWithFlags(&evC, cudaEventDisableTiming);
    }

    const int TB = 256;
    int nb = (Nn + 1023) / 1024;

    // ---- Fork: CSR build on s2, gemm1 on main stream ----
    cudaEventRecord(evF, 0);
    cudaStreamWaitEvent(s2, evF, 0);

    detect_idx_kernel<<<1, 256, 0, s2>>>(ei_raw, p_is64);
    init_cnt_kernel<<<(Nn + TB - 1) / TB, TB, 0, s2>>>(p_cnt, Nn);
    convert_hist_kernel<<<(int)((2 * E + TB - 1) / TB), TB, 0, s2>>>(ei_raw, p_idx, p_cnt, 2 * E, E, p_is64);
    scanA_kernel<<<nb, 1024, 0, s2>>>(p_cnt, p_off, p_bsum, Nn);
    scanB_kernel<<<1, 128, 0, s2>>>(p_bsum, nb);
    scanC_kernel<<<(Nn + TB - 1) / TB, TB, 0, s2>>>(p_off, p_cur, p_bsum, Nn, (int)T);
    fill_kernel<<<(int)((T + TB - 1) / TB), TB, 0, s2>>>(p_idx, p_cur, p_srcs, E, T);
    cudaEventRecord(evC, s2);

    gemm1_kernel<<<(Nn + 127) / 128, 128>>>(x, W1, a_src1, a_dst1, p_h1, p_as, p_ad, Nn);

    // ---- Join ----
    cudaStreamWaitEvent(0, evC, 0);
    gat_agg_kernel<64, false><<<(Nn + 7) / 8, 256>>>(p_srcs, p_off, p_as, p_ad, p_h1, b1, p_h1r, Nn);
    gemm2_kernel<<<(Nn + 31) / 32, 128>>>(p_h1r, W2, a_src2, a_dst2, p_h2, p_as, p_ad, Nn);
    gat_agg_kernel<40, true><<<(Nn + 7) / 8, 256>>>(p_srcs, p_off, p_as, p_ad, p_h2, b2, out, Nn);
}

// round 9
// speedup vs baseline: 1.2019x; 1.1139x over previous
#include <cuda_runtime.h>
#include <cuda_fp16.h>
#include <math.h>

// ---------------------------------------------------------------------------
// N=100000, F_in=128, F_hid=64, F_out=40, E=1600000 (+N self loops).
// h1 / h2 stored fp16 (gather traffic halved); all accumulation fp32.
// ---------------------------------------------------------------------------
#define MAXN 100000
#define MAXE 1700096

__device__ __half g_h1h[(size_t)MAXN * 64];
__device__ float  g_h1r[(size_t)MAXN * 64];
__device__ __half g_h2h[(size_t)MAXN * 40];
__device__ float  g_as[MAXN];
__device__ float  g_ad[MAXN];
__device__ int    g_cnt[MAXN];
__device__ int    g_off[MAXN + 1];
__device__ int    g_cur[MAXN];
__device__ int    g_srcs[MAXE];
__device__ int    g_bsum[128];
__device__ int    g_is64;

// ---------------------------------------------------------------------------
// Edge index dtype detection; hist + fill read the raw buffer directly.
// ---------------------------------------------------------------------------
__global__ void detect_idx_kernel(const unsigned int* __restrict__ w, int* flag) {
    __shared__ int any;
    if (threadIdx.x == 0) any = 0;
    __syncthreads();
    for (int i = threadIdx.x; i < 1024; i += blockDim.x)
        if (w[2 * i + 1] != 0u) atomicOr(&any, 1);
    __syncthreads();
    if (threadIdx.x == 0) *flag = any ? 0 : 1;  // 1 => int64
}

__global__ void init_cnt_kernel(int* cnt, int n) {
    int i = blockIdx.x * blockDim.x + threadIdx.x;
    if (i < n) cnt[i] = 1;  // self loop
}

__global__ void hist_kernel(const unsigned int* __restrict__ w,
                            int* __restrict__ cnt, long long E,
                            const int* __restrict__ flag) {
    long long i = (long long)blockIdx.x * blockDim.x + threadIdx.x;
    if (i >= E) return;
    int is64 = *flag;
    // dst half: element (E + i)
    int v = (int)(is64 ? w[2 * (E + i)] : w[E + i]);
    atomicAdd(&cnt[v], 1);
}

// ---------------------------------------------------------------------------
// Two-level exclusive scan of cnt -> off
// ---------------------------------------------------------------------------
__global__ void scanA_kernel(const int* __restrict__ cnt, int* __restrict__ off,
                             int* __restrict__ bsum, int n) {
    __shared__ int sm[1024];
    int i = blockIdx.x * 1024 + threadIdx.x;
    int v = (i < n) ? cnt[i] : 0;
    sm[threadIdx.x] = v;
    __syncthreads();
    #pragma unroll
    for (int o = 1; o < 1024; o <<= 1) {
        int t = (threadIdx.x >= o) ? sm[threadIdx.x - o] : 0;
        __syncthreads();
        sm[threadIdx.x] += t;
        __syncthreads();
    }
    if (i < n) off[i] = sm[threadIdx.x] - v;
    if (threadIdx.x == 1023) bsum[blockIdx.x] = sm[1023];
}

__global__ void scanB_kernel(int* bsum, int nb) {
    __shared__ int sm[128];
    int v = (threadIdx.x < nb) ? bsum[threadIdx.x] : 0;
    sm[threadIdx.x] = v;
    __syncthreads();
    #pragma unroll
    for (int o = 1; o < 128; o <<= 1) {
        int t = (threadIdx.x >= o) ? sm[threadIdx.x - o] : 0;
        __syncthreads();
        sm[threadIdx.x] += t;
        __syncthreads();
    }
    if (threadIdx.x < nb) bsum[threadIdx.x] = sm[threadIdx.x] - v;
}

__global__ void scanC_kernel(int* __restrict__ off, int* __restrict__ cur,
                             const int* __restrict__ bsum, int n, int total) {
    int i = blockIdx.x * blockDim.x + threadIdx.x;
    if (i < n) {
        int o = off[i] + bsum[i >> 10];
        off[i] = o;
        cur[i] = o;
    }
    if (i == 0) off[n] = total;
}

__global__ void fill_kernel(const unsigned int* __restrict__ w,
                            int* __restrict__ cur, int* __restrict__ srcs,
                            long long E, long long T,
                            const int* __restrict__ flag) {
    long long t = (long long)blockIdx.x * blockDim.x + threadIdx.x;
    if (t >= T) return;
    int is64 = *flag;
    int s, d;
    if (t < E) {
        s = (int)(is64 ? w[2 * t] : w[t]);
        d = (int)(is64 ? w[2 * (E + t)] : w[E + t]);
    } else {
        s = d = (int)(t - E);
    }
    int pos = atomicAdd(&cur[d], 1);
    srcs[pos] = s;
}

// ---------------------------------------------------------------------------
// GEMM1: h = x @ W (K=128, C=64), fp32 accumulation, fp16 output rows.
// Alpha dots computed from fp32 accumulators, fused into epilogue.
// ---------------------------------------------------------------------------
__global__ void gemm1_kernel(const float* __restrict__ x,
                             const float* __restrict__ W,
                             const float* __restrict__ asv,
                             const float* __restrict__ adv,
                             __half* __restrict__ h,
                             float* __restrict__ as_, float* __restrict__ ad_,
                             int Nn) {
    __shared__ float Xs[128 * 32];
    __shared__ float Ws[32 * 64];
    int tid = threadIdx.x;
    int row0 = blockIdx.x * 128;
    int rt = tid >> 3;
    int ct = tid & 7;
    int r0 = rt * 8;
    int kx = (rt & 3) << 3;

    unsigned long long acc[8][4];
    #pragma unroll
    for (int i = 0; i < 8; i++)
        #pragma unroll
        for (int j = 0; j < 4; j++) acc[i][j] = 0ull;

    const float4* x4 = (const float4*)x;

    for (int kc = 0; kc < 4; kc++) {
        const float4* W4 = (const float4*)(W + kc * 32 * 64);
        #pragma unroll
        for (int i = tid; i < 512; i += 128) ((float4*)Ws)[i] = W4[i];
        #pragma unroll
        for (int i = tid; i < 1024; i += 128) {
            int row = i >> 3;
            int c4  = i & 7;
            int gr = row0 + row;
            float4 v = (gr < Nn) ? x4[(size_t)gr * 32 + kc * 8 + c4]
                                 : make_float4(0.f, 0.f, 0.f, 0.f);
            int col = (c4 * 4) ^ (((row >> 3) & 3) << 3);
            *(float4*)&Xs[row * 32 + col] = v;
        }
        __syncthreads();

        #pragma unroll
        for (int k = 0; k < 32; k++) {
            longlong2 w0 = *(const longlong2*)&Ws[k * 64 + ct * 8];
            longlong2 w1 = *(const longlong2*)&Ws[k * 64 + ct * 8 + 4];
            #pragma unroll
            for (int i = 0; i < 8; i++) {
                float xv = Xs[(r0 + i) * 32 + (k ^ kx)];
                unsigned long long xx;
                asm("mov.b64 %0, {%1, %1};" : "=l"(xx) : "r"(__float_as_uint(xv)));
                asm("fma.rn.f32x2 %0, %1, %2, %0;" : "+l"(acc[i][0]) : "l"(xx), "l"((unsigned long long)w0.x));
                asm("fma.rn.f32x2 %0, %1, %2, %0;" : "+l"(acc[i][1]) : "l"(xx), "l"((unsigned long long)w0.y));
                asm("fma.rn.f32x2 %0, %1, %2, %0;" : "+l"(acc[i][2]) : "l"(xx), "l"((unsigned long long)w1.x));
                asm("fma.rn.f32x2 %0, %1, %2, %0;" : "+l"(acc[i][3]) : "l"(xx), "l"((unsigned long long)w1.y));
            }
        }
        __syncthreads();
    }

    const float4* as4 = (const float4*)asv;
    const float4* ad4 = (const float4*)adv;
    float4 sa0 = as4[ct * 2], sa1 = as4[ct * 2 + 1];
    float4 da0 = ad4[ct * 2], da1 = ad4[ct * 2 + 1];

    #pragma unroll
    for (int i = 0; i < 8; i++) {
        int row = row0 + r0 + i;
        float o[8];
        #pragma unroll
        for (int j = 0; j < 4; j++) {
            unsigned int lo, hi;
            asm("mov.b64 {%0, %1}, %2;" : "=r"(lo), "=r"(hi) : "l"(acc[i][j]));
            o[2 * j]     = __uint_as_float(lo);
            o[2 * j + 1] = __uint_as_float(hi);
        }
        float ps = o[0]*sa0.x + o[1]*sa0.y + o[2]*sa0.z + o[3]*sa0.w
                 + o[4]*sa1.x + o[5]*sa1.y + o[6]*sa1.z + o[7]*sa1.w;
        float pd = o[0]*da0.x + o[1]*da0.y + o[2]*da0.z + o[3]*da0.w
                 + o[4]*da1.x + o[5]*da1.y + o[6]*da1.z + o[7]*da1.w;
        #pragma unroll
        for (int m = 1; m < 8; m <<= 1) {
            ps += __shfl_xor_sync(0xffffffffu, ps, m);
            pd += __shfl_xor_sync(0xffffffffu, pd, m);
        }
        if (row < Nn) {
            __half2 p0 = __floats2half2_rn(o[0], o[1]);
            __half2 p1 = __floats2half2_rn(o[2], o[3]);
            __half2 p2 = __floats2half2_rn(o[4], o[5]);
            __half2 p3 = __floats2half2_rn(o[6], o[7]);
            uint4 pk;
            pk.x = *(unsigned int*)&p0; pk.y = *(unsigned int*)&p1;
            pk.z = *(unsigned int*)&p2; pk.w = *(unsigned int*)&p3;
            *(uint4*)(h + (size_t)row * 64 + ct * 8) = pk;
            if (ct == 0) { as_[row] = ps; ad_[row] = pd; }
        }
    }
}

// ---------------------------------------------------------------------------
// GEMM2: h2 = h1r @ W2 (K=64, C=40), fp16 output, alpha dots fused.
// ---------------------------------------------------------------------------
__global__ void gemm2_kernel(const float* __restrict__ x,
                             const float* __restrict__ W,
                             const float* __restrict__ asv,
                             const float* __restrict__ adv,
                             __half* __restrict__ h,
                             float* __restrict__ as_, float* __restrict__ ad_,
                             int Nn) {
    __shared__ float Xs[32][64];
    __shared__ float Ws[64][40];
    int tid = threadIdx.x;
    int row0 = blockIdx.x * 32;

    #pragma unroll
    for (int i = tid; i < 64 * 40; i += 128) Ws[i / 40][i % 40] = W[i];

    const float4* x4 = (const float4*)x;
    float4* Xs4 = (float4*)Xs;
    #pragma unroll
    for (int i = tid; i < 32 * 16; i += 128) {
        long long gi = (long long)row0 * 16 + i;
        Xs4[i] = (gi < (long long)Nn * 16) ? x4[gi] : make_float4(0.f, 0.f, 0.f, 0.f);
    }
    __syncthreads();

    int r0 = (tid >> 3) * 2;
    int c0 = (tid & 7) * 5;
    float acc[2][5] = {};
    #pragma unroll 4
    for (int k = 0; k < 64; k++) {
        float xv0 = Xs[r0][k];
        float xv1 = Xs[r0 + 1][k];
        #pragma unroll
        for (int j = 0; j < 5; j++) {
            float wv = Ws[k][c0 + j];
            acc[0][j] += xv0 * wv;
            acc[1][j] += xv1 * wv;
        }
    }

    float sa[5], da[5];
    #pragma unroll
    for (int j = 0; j < 5; j++) { sa[j] = asv[c0 + j]; da[j] = adv[c0 + j]; }

    #pragma unroll
    for (int i = 0; i < 2; i++) {
        int row = row0 + r0 + i;
        float ps = 0.f, pd = 0.f;
        #pragma unroll
        for (int j = 0; j < 5; j++) {
            ps += acc[i][j] * sa[j];
            pd += acc[i][j] * da[j];
        }
        #pragma unroll
        for (int m = 1; m < 8; m <<= 1) {
            ps += __shfl_xor_sync(0xffffffffu, ps, m);
            pd += __shfl_xor_sync(0xffffffffu, pd, m);
        }
        if (row < Nn) {
            __half* dstp = h + (size_t)row * 40 + c0;
            #pragma unroll
            for (int j = 0; j < 5; j++) dstp[j] = __float2half_rn(acc[i][j]);
            if ((tid & 7) == 0) { as_[row] = ps; ad_[row] = pd; }
        }
    }
}

// ---------------------------------------------------------------------------
// Fused GAT aggregation, one warp per destination (CSR), fp16 feature rows.
// Pass 1: lane-parallel exp (smem cache for deg<=96; else recompute).
// Pass 2: 16 edges / warp-iteration (4 per 8-lane subwarp); each lane loads
// ONE float4 (= 8 halves = its 8 feature columns) per edge. fp32 accumulate.
// Epilogue: FINAL=false -> relu(acc+bias) fp32; FINAL=true -> log_softmax.
// LROW = F/8 lanes carry data per row.
// ---------------------------------------------------------------------------
template <int F, bool FINAL>
__global__ void gat_agg_kernel(const int* __restrict__ srcs,
                               const int* __restrict__ off,
                               const float* __restrict__ as_,
                               const float* __restrict__ ad_,
                               const __half* __restrict__ h,
                               const float* __restrict__ bias,
                               float* __restrict__ outp, int Nn) {
    constexpr int LROW = F / 8;          // float4-lanes per row: 8 (F=64), 5 (F=40)
    __shared__ float exco[8][100];
    int w = threadIdx.x >> 5, lane = threadIdx.x & 31;
    int d = blockIdx.x * 8 + w;
    if (d >= Nn) return;
    int beg = off[d], end = off[d + 1];
    int deg = end - beg;
    float advv = ad_[d];
    float* exc = exco[w];
    bool fits = (deg <= 96);

    // Pass 1
    float sum = 0.f;
    for (int i = lane; i < deg; i += 32) {
        int s = srcs[beg + i];
        float e = as_[s] + advv;
        e = (e > 0.f) ? e : 0.2f * e;
        float xv = __expf(e);
        if (fits) exc[i] = xv;
        sum += xv;
    }
    #pragma unroll
    for (int m = 16; m; m >>= 1) sum += __shfl_xor_sync(0xffffffffu, sum, m);
    float rden = 1.0f / sum;
    __syncwarp();

    int g = lane >> 3, l8 = lane & 7;
    bool act = (l8 < LROW);
    float a[8] = {0.f, 0.f, 0.f, 0.f, 0.f, 0.f, 0.f, 0.f};
    const float4* h4 = (const float4*)h;

    if (fits) {
        for (int it = 0; it < deg; it += 16) {
            int e[4], idx[4], s[4];
            float c[4];
            #pragma unroll
            for (int q = 0; q < 4; q++) {
                e[q] = it + q * 4 + g;
                idx[q] = min(e[q], deg - 1);
                s[q] = srcs[beg + idx[q]];
            }
            #pragma unroll
            for (int q = 0; q < 4; q++) {
                c[q] = exc[idx[q]] * rden;
                if (e[q] >= deg) c[q] = 0.f;
            }
            float4 v[4];
            #pragma unroll
            for (int q = 0; q < 4; q++)
                if (act) v[q] = __ldg(&h4[(size_t)s[q] * LROW + l8]);
            #pragma unroll
            for (int q = 0; q < 4; q++) {
                if (act) {
                    const __half2* hp = (const __half2*)&v[q];
                    float2 f0 = __half22float2(hp[0]);
                    float2 f1 = __half22float2(hp[1]);
                    float2 f2 = __half22float2(hp[2]);
                    float2 f3 = __half22float2(hp[3]);
                    a[0] = fmaf(f0.x, c[q], a[0]); a[1] = fmaf(f0.y, c[q], a[1]);
                    a[2] = fmaf(f1.x, c[q], a[2]); a[3] = fmaf(f1.y, c[q], a[3]);
                    a[4] = fmaf(f2.x, c[q], a[4]); a[5] = fmaf(f2.y, c[q], a[5]);
                    a[6] = fmaf(f3.x, c[q], a[6]); a[7] = fmaf(f3.y, c[q], a[7]);
                }
            }
        }
    } else {
        for (int it = 0; it < deg; it += 4) {
            int e = it + g;
            if (e < deg) {
                int s = srcs[beg + e];
                float ev = as_[s] + advv;
                ev = (ev > 0.f) ? ev : 0.2f * ev;
                float coef = __expf(ev) * rden;
                if (act) {
                    float4 v = __ldg(&h4[(size_t)s * LROW + l8]);
                    const __half2* hp = (const __half2*)&v;
                    float2 f0 = __half22float2(hp[0]);
                    float2 f1 = __half22float2(hp[1]);
                    float2 f2 = __half22float2(hp[2]);
                    float2 f3 = __half22float2(hp[3]);
                    a[0] = fmaf(f0.x, coef, a[0]); a[1] = fmaf(f0.y, coef, a[1]);
                    a[2] = fmaf(f1.x, coef, a[2]); a[3] = fmaf(f1.y, coef, a[3]);
                    a[4] = fmaf(f2.x, coef, a[4]); a[5] = fmaf(f2.y, coef, a[5]);
                    a[6] = fmaf(f3.x, coef, a[6]); a[7] = fmaf(f3.y, coef, a[7]);
                }
            }
        }
    }

    // Combine the 4 subwarps (xor 8,16): afterwards lanes with equal l8 agree.
    #pragma unroll
    for (int m = 8; m < 32; m <<= 1)
        #pragma unroll
        for (int j = 0; j < 8; j++)
            a[j] += __shfl_xor_sync(0xffffffffu, a[j], m);

    if (!FINAL) {
        if (lane < LROW) {   // g==0 lanes
            float o[8];
            #pragma unroll
            for (int j = 0; j < 8; j++)
                o[j] = fmaxf(a[j] + bias[l8 * 8 + j], 0.f);
            float* dstp = outp + (size_t)d * F + l8 * 8;
            *(float4*)dstp       = make_float4(o[0], o[1], o[2], o[3]);
            *(float4*)(dstp + 4) = make_float4(o[4], o[5], o[6], o[7]);
        }
    } else {
        float v[8];
        float mx = __int_as_float(0xff800000);
        if (act) {
            #pragma unroll
            for (int j = 0; j < 8; j++) {
                v[j] = a[j] + bias[l8 * 8 + j];
                mx = fmaxf(mx, v[j]);
            }
        }
        #pragma unroll
        for (int m = 1; m < 8; m <<= 1) mx = fmaxf(mx, __shfl_xor_sync(0xffffffffu, mx, m));
        float se = 0.f;
        if (act) {
            #pragma unroll
            for (int j = 0; j < 8; j++) se += __expf(v[j] - mx);
        }
        #pragma unroll
        for (int m = 1; m < 8; m <<= 1) se += __shfl_xor_sync(0xffffffffu, se, m);
        float ls = mx + __logf(se);
        if (lane < LROW) {   // g==0 active lanes
            float* dstp = outp + (size_t)d * F + l8 * 8;
            *(float4*)dstp       = make_float4(v[0] - ls, v[1] - ls, v[2] - ls, v[3] - ls);
            *(float4*)(dstp + 4) = make_float4(v[4] - ls, v[5] - ls, v[6] - ls, v[7] - ls);
        }
    }
}

// ---------------------------------------------------------------------------
// Launch: CSR build on side stream, overlapped with gemm1.
// ---------------------------------------------------------------------------
extern "C" void kernel_launch(void* const* d_in, const int* in_sizes, int n_in,
                              void* d_out, int out_size) {
    const float* x       = (const float*)d_in[0];
    const unsigned int* ei_raw = (const unsigned int*)d_in[1];
    const float* W1      = (const float*)d_in[2];
    const float* a_src1  = (const float*)d_in[3];
    const float* a_dst1  = (const float*)d_in[4];
    const float* b1      = (const float*)d_in[5];
    const float* W2      = (const float*)d_in[6];
    const float* a_src2  = (const float*)d_in[7];
    const float* a_dst2  = (const float*)d_in[8];
    const float* b2      = (const float*)d_in[9];
    float* out           = (float*)d_out;

    int Nn = in_sizes[0] / 128;
    long long E = in_sizes[1] / 2;
    long long T = E + Nn;

    float *p_h1r, *p_as, *p_ad;
    __half *p_h1h, *p_h2h;
    int *p_cnt, *p_off, *p_cur, *p_srcs, *p_bsum, *p_is64;
    cudaGetSymbolAddress((void**)&p_h1h, g_h1h);
    cudaGetSymbolAddress((void**)&p_h1r, g_h1r);
    cudaGetSymbolAddress((void**)&p_h2h, g_h2h);
    cudaGetSymbolAddress((void**)&p_as, g_as);
    cudaGetSymbolAddress((void**)&p_ad, g_ad);
    cudaGetSymbolAddress((void**)&p_cnt, g_cnt);
    cudaGetSymbolAddress((void**)&p_off, g_off);
    cudaGetSymbolAddress((void**)&p_cur, g_cur);
    cudaGetSymbolAddress((void**)&p_srcs, g_srcs);
    cudaGetSymbolAddress((void**)&p_bsum, g_bsum);
    cudaGetSymbolAddress((void**)&p_is64, g_is64);

    static cudaStream_t s2 = nullptr;
    static cudaEvent_t evF = nullptr, evC = nullptr;
    if (!s2) {
        cudaStreamCreateWithFlags(&s2, cudaStreamNonBlocking);
        cudaEventCreateWithFlags(&evF, cudaEventDisableTiming);
        cudaEventCreateWithFlags(&evC, cudaEventDisableTiming);
    }

    const int TB = 256;
    int nb = (Nn + 1023) / 1024;

    // ---- Fork: CSR build on s2, gemm1 on main stream ----
    cudaEventRecord(evF, 0);
    cudaStreamWaitEvent(s2, evF, 0);

    detect_idx_kernel<<<1, 256, 0, s2>>>(ei_raw, p_is64);
    init_cnt_kernel<<<(Nn + TB - 1) / TB, TB, 0, s2>>>(p_cnt, Nn);
    hist_kernel<<<(int)((E + TB - 1) / TB), TB, 0, s2>>>(ei_raw, p_cnt, E, p_is64);
    scanA_kernel<<<nb, 1024, 0, s2>>>(p_cnt, p_off, p_bsum, Nn);
    scanB_kernel<<<1, 128, 0, s2>>>(p_bsum, nb);
    scanC_kernel<<<(Nn + TB - 1) / TB, TB, 0, s2>>>(p_off, p_cur, p_bsum, Nn, (int)T);
    fill_kernel<<<(int)((T + TB - 1) / TB), TB, 0, s2>>>(ei_raw, p_cur, p_srcs, E, T, p_is64);
    cudaEventRecord(evC, s2);

    gemm1_kernel<<<(Nn + 127) / 128, 128>>>(x, W1, a_src1, a_dst1, p_h1h, p_as, p_ad, Nn);

    // ---- Join ----
    cudaStreamWaitEvent(0, evC, 0);
    gat_agg_kernel<64, false><<<(Nn + 7) / 8, 256>>>(p_srcs, p_off, p_as, p_ad, p_h1h, b1, p_h1r, Nn);
    gemm2_kernel<<<(Nn + 31) / 32, 128>>>(p_h1r, W2, a_src2, a_dst2, p_h2h, p_as, p_ad, Nn);
    gat_agg_kernel<40, true><<<(Nn + 7) / 8, 256>>>(p_srcs, p_off, p_as, p_ad, p_h2h, b2, out, Nn);
}